// round 5
// baseline (speedup 1.0000x reference)
#include <cuda_runtime.h>

#define TT 4096
#define BB 128
#define CC 46
#define LL 43
#define CHUNKS 32           /* TT / 128 */
#define NINF (-3.4e38f)

// ---------------- scratch (static device globals; no allocation) ----------------
__device__ float4 g_cmats[BB * CHUNKS];   // per-(batch,chunk) normalized prob matrix
__device__ float  g_cscl[BB * CHUNKS];    // log-scale of that matrix
__device__ float  g_numpart[BB * CHUNKS];
__device__ float  g_res[BB];
__device__ int    g_cnt[BB];              // zero-init (BSS); self-resetting
__device__ int    g_cnt_all;              // zero-init; self-resetting

// ---------------- scaled-probability semiring matrix ----------------
// value = exp(s) * P, P 2x2 row-major: x=00, y=01, z=10, w=11, max entry = 1.
struct SMat { float4 p; float s; };

// C = A (later) * B (earlier): 8 FFMA + rcp + log (2 MUFU).
__device__ __forceinline__ SMat smul(const SMat A, const SMat B) {
    SMat C;
    C.p.x = fmaf(A.p.x, B.p.x, A.p.y * B.p.z);
    C.p.y = fmaf(A.p.x, B.p.y, A.p.y * B.p.w);
    C.p.z = fmaf(A.p.z, B.p.x, A.p.w * B.p.z);
    C.p.w = fmaf(A.p.z, B.p.y, A.p.w * B.p.w);
    float mx = fmaxf(fmaxf(C.p.x, C.p.y), fmaxf(C.p.z, C.p.w));
    float r  = __fdividef(1.0f, mx);
    C.p.x *= r; C.p.y *= r; C.p.z *= r; C.p.w *= r;
    C.s = A.s + B.s + __logf(mx);
    return C;
}

__device__ __forceinline__ SMat shfl_down_m(const SMat v, int s, int w) {
    SMat r;
    r.p.x = __shfl_down_sync(0xffffffffu, v.p.x, s, w);
    r.p.y = __shfl_down_sync(0xffffffffu, v.p.y, s, w);
    r.p.z = __shfl_down_sync(0xffffffffu, v.p.z, s, w);
    r.p.w = __shfl_down_sync(0xffffffffu, v.p.w, s, w);
    r.s   = __shfl_down_sync(0xffffffffu, v.s,   s, w);
    return r;
}

// ---------------- k1: fully fused kernel ----------------
// grid (TT/128, BB), block 128 threads, thread = one timestep.
__global__ void __launch_bounds__(128) k1_main(
    const float* __restrict__ lp,
    const float* __restrict__ dp,
    const int* __restrict__ lens,
    const int* __restrict__ labels,
    float* __restrict__ out)
{
    __shared__ float  tile[128 * CC];     // 23552 B
    __shared__ float2 wab[CC];            // (w0, w1) interleaved
    __shared__ float  scs[4];             // [0]=s_0I, [1]=exp(s_1I-s_0I), [2]=s_fin
    __shared__ float4 warpP[4];
    __shared__ float  warpS[4];
    __shared__ float  warpT[4];

    const int tid  = threadIdx.x;
    const int lane = tid & 31;
    const int wid  = tid >> 5;
    const int b    = blockIdx.y;
    const int tb   = blockIdx.x * 128;

    // --- warp 0: recompute softmax weights from den_params (L2 broadcast) ---
    if (wid == 0) {
        float a  = dp[lane];
        float bb = (lane + 32 < CC) ? dp[lane + 32] : NINF;
        float m = fmaxf(a, bb);
#pragma unroll
        for (int o = 16; o; o >>= 1) m = fmaxf(m, __shfl_xor_sync(0xffffffffu, m, o));
        float s = __expf(a - m) + __expf(bb - m);
#pragma unroll
        for (int o = 16; o; o >>= 1) s += __shfl_xor_sync(0xffffffffu, s, o);
        const float lz0 = m + __logf(s);
        float a1 = (lane < LL + 1) ? dp[CC + lane] : NINF;
        float b1 = (lane + 32 < LL + 1) ? dp[CC + lane + 32] : NINF;
        float m1 = fmaxf(a1, b1);
#pragma unroll
        for (int o = 16; o; o >>= 1) m1 = fmaxf(m1, __shfl_xor_sync(0xffffffffu, m1, o));
        float s1 = __expf(a1 - m1) + __expf(b1 - m1);
#pragma unroll
        for (int o = 16; o; o >>= 1) s1 += __shfl_xor_sync(0xffffffffu, s1, o);
        const float lz1 = m1 + __logf(s1);

#pragma unroll
        for (int c = lane; c < CC; c += 32) {
            float w0 = 0.f, w1 = 0.f;
            if (c == 1) w0 = __expf(dp[0] - lz0);          // exp(s_O) folded into S0
            if (c >= 3) {
                w0 = __expf(dp[c - 2] - lz0);              // exp(s0_lab[c-3])
                w1 = __expf(dp[CC + c - 2] - lz1);         // exp(s1_lab[c-3])
            }
            wab[c] = make_float2(w0, w1);
        }
        if (lane == 0) {
            const float s0I = dp[LL + 1] - lz0;
            const float s1I = dp[CC] - lz1;
            scs[0] = s0I;
            scs[1] = __expf(s1I - s0I);
            scs[2] = dp[LL + 2] - lz0;   // s_fin
        }
    }

    // --- coalesced float4 staging: 128 rows x 46 floats = 1472 float4 ---
    const float4* __restrict__ src = (const float4*)(lp + ((size_t)b * TT + tb) * CC);
    float4* dst = (float4*)tile;
#pragma unroll
    for (int i = 0; i < 11; i++) dst[tid + i * 128] = src[tid + i * 128];
    {
        int i = tid + 11 * 128;
        if (i < 1472) dst[i] = src[i];
    }
    __syncthreads();

    // per-thread row: 23 float2 LDS, stride 46 floats -> conflict-free
    float v[CC];
    const float2* r2 = (const float2*)(tile + tid * CC);
#pragma unroll
    for (int i = 0; i < 23; i++) { float2 q = r2[i]; v[2 * i] = q.x; v[2 * i + 1] = q.y; }

    // shared max over weighted columns {1, 3..45}
    float m = v[1];
#pragma unroll
    for (int c = 3; c < CC; c++) m = fmaxf(m, v[c]);

    float S0 = __expf(v[1] - m) * wab[1].x;
    float S1 = 0.f;
#pragma unroll
    for (int c = 3; c < CC; c++) {
        float e = __expf(v[c] - m);
        float2 w = wab[c];
        S0 = fmaf(e, w.x, S0);
        S1 = fmaf(e, w.y, S1);
    }

    const float lp2 = v[2];
    const int  t     = tb + tid;
    const bool valid = t < lens[b];
    const int  lab   = labels[(size_t)b * TT + t];
    float tok        = valid ? tile[tid * CC + lab] : 0.f;

    SMat M;
    if (valid) {
        const float p10 = __expf(scs[0] + lp2 - m);
        M.p = make_float4(S0, S1, p10, p10 * scs[1]);
        M.s = m;
    } else {
        M.p = make_float4(1.f, 0.f, 0.f, 1.f);   // identity
        M.s = 0.f;
    }

    // masked token-logprob warp sum
#pragma unroll
    for (int o = 16; o; o >>= 1) tok += __shfl_xor_sync(0xffffffffu, tok, o);

    // --- warp-level ordered fold (later * earlier) ---
#pragma unroll
    for (int s = 1; s < 32; s <<= 1) {
        SMat o = shfl_down_m(M, s, 32);
        if ((lane & (2 * s - 1)) == 0) M = smul(o, M);
    }
    if (lane == 0) { warpP[wid] = M.p; warpS[wid] = M.s; warpT[wid] = tok; }
    __syncthreads();

    // --- warp 0: combine 4 warp results, publish, maybe close ---
    if (wid == 0) {
        SMat A;
        if (lane < 4) { A.p = warpP[lane]; A.s = warpS[lane]; }
        else          { A.p = make_float4(1.f, 0.f, 0.f, 1.f); A.s = 0.f; }
#pragma unroll
        for (int s = 1; s < 4; s <<= 1) {
            SMat o = shfl_down_m(A, s, 4);
            if ((lane & (2 * s - 1)) == 0 && lane + s < 4) A = smul(o, A);
        }

        const int slot = b * CHUNKS + blockIdx.x;
        int old = 0;
        if (lane == 0) {
            g_cmats[slot]   = A.p;
            g_cscl[slot]    = A.s;
            g_numpart[slot] = warpT[0] + warpT[1] + warpT[2] + warpT[3];
            __threadfence();
            old = atomicAdd(&g_cnt[b], 1);
        }
        old = __shfl_sync(0xffffffffu, old, 0);

        // --- batch closer: fold this batch's 32 chunk matrices ---
        if (old == CHUNKS - 1) {
            __threadfence();
            SMat P;
            P.p = g_cmats[b * CHUNKS + lane];
            P.s = g_cscl[b * CHUNKS + lane];
            float np = g_numpart[b * CHUNKS + lane];
#pragma unroll
            for (int s = 1; s < 32; s <<= 1) {
                SMat o = shfl_down_m(P, s, 32);
                if ((lane & (2 * s - 1)) == 0) P = smul(o, P);
            }
#pragma unroll
            for (int o = 16; o; o >>= 1) np += __shfl_xor_sync(0xffffffffu, np, o);

            int old2 = 0;
            if (lane == 0) {
                // alpha0=[1,0]: den = s + log(P00) + s_fin
                const float den = P.s + __logf(P.p.x) + scs[2];
                g_res[b] = np - den;
                g_cnt[b] = 0;                 // reset for next graph replay
                __threadfence();
                old2 = atomicAdd(&g_cnt_all, 1);
            }
            old2 = __shfl_sync(0xffffffffu, old2, 0);

            // --- global closer: sum 128 batch results ---
            if (old2 == BB - 1) {
                __threadfence();
                float s = g_res[lane] + g_res[lane + 32] + g_res[lane + 64] + g_res[lane + 96];
#pragma unroll
                for (int o = 16; o; o >>= 1) s += __shfl_xor_sync(0xffffffffu, s, o);
                if (lane == 0) {
                    out[0] = s;
                    g_cnt_all = 0;            // reset for next graph replay
                }
            }
        }
    }
}

// ---------------- launcher ----------------
extern "C" void kernel_launch(void* const* d_in, const int* in_sizes, int n_in,
                              void* d_out, int out_size) {
    const float* lp     = (const float*)d_in[0];  // (B,T,C) float32
    const float* dp     = (const float*)d_in[1];  // (2L+4,) float32
    const int*   lens   = (const int*)d_in[2];    // (B,) int32
    const int*   labels = (const int*)d_in[3];    // (B,T) int32

    dim3 grid(TT / 128, BB);
    k1_main<<<grid, 128>>>(lp, dp, lens, labels, (float*)d_out);
}

// round 7
// speedup vs baseline: 1.1484x; 1.1484x over previous
#include <cuda_runtime.h>
#include <cstdint>

#define TT 4096
#define BB 128
#define CC 46
#define LL 43
#define NCH 4                 /* chunks (of 128 timesteps) per block */
#define CHB 8                 /* blocks per batch = TT/(128*NCH) */
#define NINF (-3.4e38f)

// ---------------- scratch (static device globals; no allocation) ----------------
__device__ float4 g_cmats[BB * CHB];
__device__ float  g_cscl[BB * CHB];
__device__ float  g_numpart[BB * CHB];

// ---------------- scaled-probability semiring matrix ----------------
// value = exp(s) * P, P 2x2 row-major: x=00, y=01, z=10, w=11, max entry = 1.
struct SMat { float4 p; float s; };

__device__ __forceinline__ SMat smul(const SMat A, const SMat B) {
    SMat C;
    C.p.x = fmaf(A.p.x, B.p.x, A.p.y * B.p.z);
    C.p.y = fmaf(A.p.x, B.p.y, A.p.y * B.p.w);
    C.p.z = fmaf(A.p.z, B.p.x, A.p.w * B.p.z);
    C.p.w = fmaf(A.p.z, B.p.y, A.p.w * B.p.w);
    float mx = fmaxf(fmaxf(C.p.x, C.p.y), fmaxf(C.p.z, C.p.w));
    float r  = __fdividef(1.0f, mx);
    C.p.x *= r; C.p.y *= r; C.p.z *= r; C.p.w *= r;
    C.s = A.s + B.s + __logf(mx);
    return C;
}

__device__ __forceinline__ SMat shfl_down_m(const SMat v, int s, int w) {
    SMat r;
    r.p.x = __shfl_down_sync(0xffffffffu, v.p.x, s, w);
    r.p.y = __shfl_down_sync(0xffffffffu, v.p.y, s, w);
    r.p.z = __shfl_down_sync(0xffffffffu, v.p.z, s, w);
    r.p.w = __shfl_down_sync(0xffffffffu, v.p.w, s, w);
    r.s   = __shfl_down_sync(0xffffffffu, v.s,   s, w);
    return r;
}

__device__ __forceinline__ void cp16(uint32_t dst, const float4* src) {
    asm volatile("cp.async.cg.shared.global [%0], [%1], 16;\n" :: "r"(dst), "l"(src));
}

// ---------------- k1: pipelined streaming kernel ----------------
// grid (CHB, BB), block 128 threads; each block handles NCH chunks of 128 steps.
__global__ void __launch_bounds__(128) k1_main(
    const float* __restrict__ lp,
    const float* __restrict__ dp,
    const int* __restrict__ lens,
    const int* __restrict__ labels)
{
    __shared__ float  tiles[2][128 * CC];   // 2 x 23552 B
    __shared__ float2 wab[CC];
    __shared__ float  scs[2];               // [0]=s_0I, [1]=exp(s_1I-s_0I)
    __shared__ float4 warpP[4];
    __shared__ float  warpS[4];
    __shared__ float  warpT[4];

    const int tid  = threadIdx.x;
    const int lane = tid & 31;
    const int wid  = tid >> 5;
    const int b    = blockIdx.y;
    const int t0   = blockIdx.x * (128 * NCH);

    const float4* __restrict__ base = (const float4*)(lp + ((size_t)b * TT + t0) * CC);
    const uint32_t sm0 = (uint32_t)__cvta_generic_to_shared(&tiles[0][0]);
    const uint32_t sm1 = (uint32_t)__cvta_generic_to_shared(&tiles[1][0]);

    // --- prefetch chunk 0 into buffer 0 ---
#pragma unroll
    for (int k = 0; k < 12; k++) {
        int i = tid + k * 128;
        if (i < 1472) cp16(sm0 + i * 16, base + i);
    }
    asm volatile("cp.async.commit_group;\n");

    // --- warp 0: params (overlaps prefetch latency) ---
    if (wid == 0) {
        float a  = dp[lane];
        float bb = (lane + 32 < CC) ? dp[lane + 32] : NINF;
        float m = fmaxf(a, bb);
#pragma unroll
        for (int o = 16; o; o >>= 1) m = fmaxf(m, __shfl_xor_sync(0xffffffffu, m, o));
        float s = __expf(a - m) + __expf(bb - m);
#pragma unroll
        for (int o = 16; o; o >>= 1) s += __shfl_xor_sync(0xffffffffu, s, o);
        const float lz0 = m + __logf(s);
        float a1 = (lane < LL + 1) ? dp[CC + lane] : NINF;
        float b1 = (lane + 32 < LL + 1) ? dp[CC + lane + 32] : NINF;
        float m1 = fmaxf(a1, b1);
#pragma unroll
        for (int o = 16; o; o >>= 1) m1 = fmaxf(m1, __shfl_xor_sync(0xffffffffu, m1, o));
        float s1 = __expf(a1 - m1) + __expf(b1 - m1);
#pragma unroll
        for (int o = 16; o; o >>= 1) s1 += __shfl_xor_sync(0xffffffffu, s1, o);
        const float lz1 = m1 + __logf(s1);
#pragma unroll
        for (int c = lane; c < CC; c += 32) {
            float w0 = 0.f, w1 = 0.f;
            if (c == 1) w0 = __expf(dp[0] - lz0);
            if (c >= 3) {
                w0 = __expf(dp[c - 2] - lz0);
                w1 = __expf(dp[CC + c - 2] - lz1);
            }
            wab[c] = make_float2(w0, w1);
        }
        if (lane == 0) {
            const float s0I = dp[LL + 1] - lz0;
            scs[0] = s0I;
            scs[1] = __expf((dp[CC] - lz1) - s0I);
        }
    }

    const int len = lens[b];
    float tok_acc = 0.f;
    SMat run;   // meaningful on warp 0 lane 0 only

    for (int c = 0; c < NCH; c++) {
        // prefetch next chunk, wait for current
        if (c + 1 < NCH) {
            const uint32_t dsm = ((c + 1) & 1) ? sm1 : sm0;
            const float4* src = base + (size_t)(c + 1) * 1472;
#pragma unroll
            for (int k = 0; k < 12; k++) {
                int i = tid + k * 128;
                if (i < 1472) cp16(dsm + i * 16, src + i);
            }
            asm volatile("cp.async.commit_group;\n");
            asm volatile("cp.async.wait_group 1;\n");
        } else {
            asm volatile("cp.async.wait_group 0;\n");
        }
        __syncthreads();    // tile[c&1] ready; warpP from prev chunk consumed

        const float* tile = tiles[c & 1];
        const int t = t0 + c * 128 + tid;
        const int lab = labels[(size_t)b * TT + t];      // issue gmem load early
        const bool valid = t < len;

        // per-thread row: 23 float2 LDS
        float v[CC];
        const float2* r2 = (const float2*)(tile + tid * CC);
#pragma unroll
        for (int i = 0; i < 23; i++) { float2 q = r2[i]; v[2 * i] = q.x; v[2 * i + 1] = q.y; }

        // 4-way split max over {1, 3..45}
        float ma = v[1], mb = v[3], mc = v[4], md = v[5];
#pragma unroll
        for (int cc2 = 6; cc2 < CC; cc2 += 4) {
            ma = fmaxf(ma, v[cc2]);
            mb = fmaxf(mb, v[cc2 + 1]);
            mc = fmaxf(mc, v[cc2 + 2]);
            md = fmaxf(md, v[cc2 + 3]);
        }
        const float m = fmaxf(fmaxf(ma, mb), fmaxf(mc, md));

        // 2-way split weighted sums over pairs (3,4)..(43,44); 45 handled after
        float S0a = __expf(v[1] - m) * wab[1].x, S0b = 0.f;
        float S1a = 0.f, S1b = 0.f;
#pragma unroll
        for (int cc2 = 3; cc2 < 45; cc2 += 2) {
            float e0 = __expf(v[cc2] - m);
            float e1 = __expf(v[cc2 + 1] - m);
            float2 w0 = wab[cc2];
            float2 w1 = wab[cc2 + 1];
            S0a = fmaf(e0, w0.x, S0a); S1a = fmaf(e0, w0.y, S1a);
            S0b = fmaf(e1, w1.x, S0b); S1b = fmaf(e1, w1.y, S1b);
        }
        {   // leftover column 45
            float e = __expf(v[45] - m);
            float2 w = wab[45];
            S0a = fmaf(e, w.x, S0a); S1a = fmaf(e, w.y, S1a);
        }

        float tok = valid ? tile[tid * CC + lab] : 0.f;
        tok_acc += tok;

        SMat M;
        if (valid) {
            const float p10 = __expf(scs[0] + v[2] - m);
            M.p = make_float4(S0a + S0b, S1a + S1b, p10, p10 * scs[1]);
            M.s = m;
        } else {
            M.p = make_float4(1.f, 0.f, 0.f, 1.f);
            M.s = 0.f;
        }

        // warp-level ordered fold
#pragma unroll
        for (int s = 1; s < 32; s <<= 1) {
            SMat o = shfl_down_m(M, s, 32);
            if ((lane & (2 * s - 1)) == 0) M = smul(o, M);
        }
        if (lane == 0) { warpP[wid] = M.p; warpS[wid] = M.s; }
        __syncthreads();

        if (wid == 0) {
            SMat A;
            if (lane < 4) { A.p = warpP[lane]; A.s = warpS[lane]; }
            else          { A.p = make_float4(1.f, 0.f, 0.f, 1.f); A.s = 0.f; }
#pragma unroll
            for (int s = 1; s < 4; s <<= 1) {
                SMat o = shfl_down_m(A, s, 4);
                if ((lane & (2 * s - 1)) == 0 && lane + s < 4) A = smul(o, A);
            }
            if (lane == 0) run = (c == 0) ? A : smul(A, run);
        }
    }

    // --- final: token sum + publish ---
#pragma unroll
    for (int o = 16; o; o >>= 1) tok_acc += __shfl_xor_sync(0xffffffffu, tok_acc, o);
    if (lane == 0) warpT[wid] = tok_acc;
    __syncthreads();
    if (tid == 0) {
        const int slot = b * CHB + blockIdx.x;
        g_cmats[slot]   = run.p;
        g_cscl[slot]    = run.s;
        g_numpart[slot] = warpT[0] + warpT[1] + warpT[2] + warpT[3];
    }
}

// ---------------- k2: chunk reduce + den + num + global sum ----------------
// one block, 1024 threads; 8 lanes per batch.
__global__ void __launch_bounds__(1024) k2_final(
    const float* __restrict__ dp, float* __restrict__ out)
{
    const int tid  = threadIdx.x;
    const int lane = tid & 31;
    const int wid  = tid >> 5;
    __shared__ float s_fin_sh;
    __shared__ float resv[BB];
    __shared__ float red[32];

    if (wid == 0) {
        float a  = dp[lane];
        float bb = (lane + 32 < CC) ? dp[lane + 32] : NINF;
        float m = fmaxf(a, bb);
#pragma unroll
        for (int o = 16; o; o >>= 1) m = fmaxf(m, __shfl_xor_sync(0xffffffffu, m, o));
        float s = __expf(a - m) + __expf(bb - m);
#pragma unroll
        for (int o = 16; o; o >>= 1) s += __shfl_xor_sync(0xffffffffu, s, o);
        if (lane == 0) s_fin_sh = dp[LL + 2] - (m + __logf(s));
    }

    const int b = tid >> 3;
    const int g = tid & 7;
    SMat M;
    M.p = g_cmats[b * CHB + g];
    M.s = g_cscl[b * CHB + g];
    float np = g_numpart[b * CHB + g];

#pragma unroll
    for (int s = 1; s < 8; s <<= 1) {
        SMat o = shfl_down_m(M, s, 8);
        if ((g & (2 * s - 1)) == 0) M = smul(o, M);
    }
#pragma unroll
    for (int s = 4; s; s >>= 1) np += __shfl_down_sync(0xffffffffu, np, s, 8);

    __syncthreads();
    if (g == 0) {
        float den = M.s + __logf(M.p.x) + s_fin_sh;   // alpha0=[1,0] in prob space
        resv[b] = np - den;
    }
    __syncthreads();

    float vv = (tid < BB) ? resv[tid] : 0.f;
#pragma unroll
    for (int o = 16; o; o >>= 1) vv += __shfl_xor_sync(0xffffffffu, vv, o);
    if (lane == 0) red[wid] = vv;
    __syncthreads();
    if (tid == 0) {
        float tsum = 0.f;
#pragma unroll
        for (int i = 0; i < 32; i++) tsum += red[i];
        out[0] = tsum;
    }
}

// ---------------- launcher ----------------
extern "C" void kernel_launch(void* const* d_in, const int* in_sizes, int n_in,
                              void* d_out, int out_size) {
    const float* lp     = (const float*)d_in[0];
    const float* dp     = (const float*)d_in[1];
    const int*   lens   = (const int*)d_in[2];
    const int*   labels = (const int*)d_in[3];

    dim3 grid(CHB, BB);
    k1_main<<<grid, 128>>>(lp, dp, lens, labels);
    k2_final<<<1, 1024>>>(dp, (float*)d_out);
}

// round 8
// speedup vs baseline: 1.3142x; 1.1444x over previous
#include <cuda_runtime.h>
#include <cstdint>

#define TT 4096
#define BB 128
#define CC 46
#define LL 43
#define NCH 4                 /* chunks (of 32 timesteps per warp) per block */
#define CHB 8                 /* blocks per batch = TT/(128*NCH) */
#define NINF (-3.4e38f)

// ---------------- scratch (static device globals; no allocation) ----------------
__device__ float4 g_cmats[BB * CHB];
__device__ float  g_cscl[BB * CHB];
__device__ float  g_numpart[BB * CHB];

// ---------------- scaled-probability semiring matrix ----------------
// value = exp(s) * P, P 2x2 row-major: x=00, y=01, z=10, w=11.
struct SMat { float4 p; float s; };

__device__ __forceinline__ SMat smul(const SMat A, const SMat B) {
    SMat C;
    C.p.x = fmaf(A.p.x, B.p.x, A.p.y * B.p.z);
    C.p.y = fmaf(A.p.x, B.p.y, A.p.y * B.p.w);
    C.p.z = fmaf(A.p.z, B.p.x, A.p.w * B.p.z);
    C.p.w = fmaf(A.p.z, B.p.y, A.p.w * B.p.w);
    float mx = fmaxf(fmaxf(C.p.x, C.p.y), fmaxf(C.p.z, C.p.w));
    float r  = __fdividef(1.0f, mx);
    C.p.x *= r; C.p.y *= r; C.p.z *= r; C.p.w *= r;
    C.s = A.s + B.s + __logf(mx);
    return C;
}

__device__ __forceinline__ SMat shfl_down_m(const SMat v, int s, int w) {
    SMat r;
    r.p.x = __shfl_down_sync(0xffffffffu, v.p.x, s, w);
    r.p.y = __shfl_down_sync(0xffffffffu, v.p.y, s, w);
    r.p.z = __shfl_down_sync(0xffffffffu, v.p.z, s, w);
    r.p.w = __shfl_down_sync(0xffffffffu, v.p.w, s, w);
    r.s   = __shfl_down_sync(0xffffffffu, v.s,   s, w);
    return r;
}

__device__ __forceinline__ void cp16(uint32_t dst, const float4* src) {
    asm volatile("cp.async.cg.shared.global [%0], [%1], 16;\n" :: "r"(dst), "l"(src));
}

// ---------------- k1: warp-private pipelined streaming kernel ----------------
// grid (CHB, BB), block 128 threads. Block covers 512 timesteps; warp w owns
// the contiguous range [t0+128w, t0+128w+128), processed as NCH chunks of 32.
__global__ void __launch_bounds__(128) k1_main(
    const float* __restrict__ lp,
    const float* __restrict__ dp,
    const int* __restrict__ lens,
    const int* __restrict__ labels)
{
    __shared__ float  tiles[2][128 * CC];   // 2 x 23552 B; warp w rows [32w,32w+32)
    __shared__ float2 wab[CC];              // (w0, w1) per column; cols 0,2 zeroed
    __shared__ float  scs[2];               // [0]=exp(s_0I), [1]=exp(s_1I)
    __shared__ float4 warpP[4];
    __shared__ float  warpS[4];
    __shared__ float  warpT[4];

    const int tid  = threadIdx.x;
    const int lane = tid & 31;
    const int wid  = tid >> 5;
    const int b    = blockIdx.y;
    const int t0   = blockIdx.x * (128 * NCH);

    const float4* __restrict__ base4 =
        (const float4*)(lp + ((size_t)b * TT + t0) * CC) + (size_t)wid * 1472;
    const uint32_t smA = (uint32_t)__cvta_generic_to_shared(&tiles[0][0]) + wid * 368 * 16;
    const uint32_t smB = (uint32_t)__cvta_generic_to_shared(&tiles[1][0]) + wid * 368 * 16;

    // --- warp-local prefetch of chunk 0 (368 float4 per warp) ---
#pragma unroll
    for (int k = 0; k < 12; k++) {
        int i = lane + 32 * k;
        if (i < 368) cp16(smA + i * 16, base4 + i);
    }
    asm volatile("cp.async.commit_group;\n");

    // --- warp 0: params (overlaps prefetch latency) ---
    if (wid == 0) {
        float a  = dp[lane];
        float bb = (lane + 32 < CC) ? dp[lane + 32] : NINF;
        float m = fmaxf(a, bb);
#pragma unroll
        for (int o = 16; o; o >>= 1) m = fmaxf(m, __shfl_xor_sync(0xffffffffu, m, o));
        float s = __expf(a - m) + __expf(bb - m);
#pragma unroll
        for (int o = 16; o; o >>= 1) s += __shfl_xor_sync(0xffffffffu, s, o);
        const float lz0 = m + __logf(s);
        float a1 = (lane < LL + 1) ? dp[CC + lane] : NINF;
        float b1 = (lane + 32 < LL + 1) ? dp[CC + lane + 32] : NINF;
        float m1 = fmaxf(a1, b1);
#pragma unroll
        for (int o = 16; o; o >>= 1) m1 = fmaxf(m1, __shfl_xor_sync(0xffffffffu, m1, o));
        float s1 = __expf(a1 - m1) + __expf(b1 - m1);
#pragma unroll
        for (int o = 16; o; o >>= 1) s1 += __shfl_xor_sync(0xffffffffu, s1, o);
        const float lz1 = m1 + __logf(s1);
#pragma unroll
        for (int c = lane; c < CC; c += 32) {
            float w0 = 0.f, w1 = 0.f;
            if (c == 1) w0 = __expf(dp[0] - lz0);          // exp(s_O): folds s_O+lp1 into S0
            if (c >= 3) {
                w0 = __expf(dp[c - 2] - lz0);              // exp(s0_lab)
                w1 = __expf(dp[CC + c - 2] - lz1);         // exp(s1_lab)
            }
            wab[c] = make_float2(w0, w1);
        }
        if (lane == 0) {
            scs[0] = __expf(dp[LL + 1] - lz0);   // exp(s_0I)
            scs[1] = __expf(dp[CC] - lz1);       // exp(s_1I)
        }
    }
    __syncthreads();   // wab/scs visible to all warps; no more block barriers until the end

    const int len = lens[b];
    const float k0 = scs[0], k1c = scs[1];
    float tok_acc = 0.f;
    SMat run;   // meaningful on lane 0 of each warp

    for (int c = 0; c < NCH; c++) {
        // warp-local prefetch of next chunk, then wait for current
        if (c + 1 < NCH) {
            const uint32_t dsm = ((c + 1) & 1) ? smB : smA;
            const float4* src = base4 + (size_t)(c + 1) * 368;
#pragma unroll
            for (int k = 0; k < 12; k++) {
                int i = lane + 32 * k;
                if (i < 368) cp16(dsm + i * 16, src + i);
            }
            asm volatile("cp.async.commit_group;\n");
            asm volatile("cp.async.wait_group 1;\n");
        } else {
            asm volatile("cp.async.wait_group 0;\n");
        }
        __syncwarp();   // warp-local: only this warp wrote & reads its segment

        const float* rowp = tiles[c & 1] + tid * CC;   // row tid = warp segment row
        const int t = t0 + wid * 128 + c * 32 + lane;
        const int lab = labels[(size_t)b * TT + t];
        const bool valid = t < len;

        // stream 23 float2: exp directly (inputs are log-softmax <= 0: no overflow)
        float S0a = 0.f, S0b = 0.f, S1a = 0.f, S1b = 0.f, e2 = 0.f;
        const float2* r2 = (const float2*)rowp;
#pragma unroll
        for (int i = 0; i < 23; i++) {
            float2 q = r2[i];
            float ex = __expf(q.x);
            float ey = __expf(q.y);
            if (i == 1) e2 = ex;                       // exp(lp[2])
            float2 wA = wab[2 * i];
            float2 wB = wab[2 * i + 1];
            S0a = fmaf(ex, wA.x, S0a); S1a = fmaf(ex, wA.y, S1a);
            S0b = fmaf(ey, wB.x, S0b); S1b = fmaf(ey, wB.y, S1b);
        }
        tok_acc += valid ? rowp[lab] : 0.f;

        SMat M;
        if (valid) {
            M.p = make_float4(S0a + S0b, S1a + S1b, e2 * k0, e2 * k1c);
            M.s = 0.f;
        } else {
            M.p = make_float4(1.f, 0.f, 0.f, 1.f);
            M.s = 0.f;
        }

        // warp-level ordered fold over 32 consecutive timesteps
#pragma unroll
        for (int s = 1; s < 32; s <<= 1) {
            SMat o = shfl_down_m(M, s, 32);
            if ((lane & (2 * s - 1)) == 0) M = smul(o, M);
        }
        run = (c == 0) ? M : smul(M, run);   // valid on lane 0
    }

    // token warp sum; publish per-warp results
#pragma unroll
    for (int o = 16; o; o >>= 1) tok_acc += __shfl_xor_sync(0xffffffffu, tok_acc, o);
    if (lane == 0) { warpP[wid] = run.p; warpS[wid] = run.s; warpT[wid] = tok_acc; }
    __syncthreads();

    if (wid == 0) {
        SMat A;
        if (lane < 4) { A.p = warpP[lane]; A.s = warpS[lane]; }
        else          { A.p = make_float4(1.f, 0.f, 0.f, 1.f); A.s = 0.f; }
#pragma unroll
        for (int s = 1; s < 4; s <<= 1) {
            SMat o = shfl_down_m(A, s, 4);
            if ((lane & (2 * s - 1)) == 0 && lane + s < 4) A = smul(o, A);
        }
        if (lane == 0) {
            const int slot = b * CHB + blockIdx.x;
            g_cmats[slot]   = A.p;
            g_cscl[slot]    = A.s;
            g_numpart[slot] = warpT[0] + warpT[1] + warpT[2] + warpT[3];
        }
    }
}

// ---------------- k2: chunk reduce + den + num + global sum ----------------
// one block, 1024 threads; 8 lanes per batch.
__global__ void __launch_bounds__(1024) k2_final(
    const float* __restrict__ dp, float* __restrict__ out)
{
    const int tid  = threadIdx.x;
    const int lane = tid & 31;
    const int wid  = tid >> 5;
    __shared__ float s_fin_sh;
    __shared__ float resv[BB];
    __shared__ float red[32];

    if (wid == 0) {
        float a  = dp[lane];
        float bb = (lane + 32 < CC) ? dp[lane + 32] : NINF;
        float m = fmaxf(a, bb);
#pragma unroll
        for (int o = 16; o; o >>= 1) m = fmaxf(m, __shfl_xor_sync(0xffffffffu, m, o));
        float s = __expf(a - m) + __expf(bb - m);
#pragma unroll
        for (int o = 16; o; o >>= 1) s += __shfl_xor_sync(0xffffffffu, s, o);
        if (lane == 0) s_fin_sh = dp[LL + 2] - (m + __logf(s));
    }

    const int b = tid >> 3;
    const int g = tid & 7;
    SMat M;
    M.p = g_cmats[b * CHB + g];
    M.s = g_cscl[b * CHB + g];
    float np = g_numpart[b * CHB + g];

#pragma unroll
    for (int s = 1; s < 8; s <<= 1) {
        SMat o = shfl_down_m(M, s, 8);
        if ((g & (2 * s - 1)) == 0) M = smul(o, M);
    }
#pragma unroll
    for (int s = 4; s; s >>= 1) np += __shfl_down_sync(0xffffffffu, np, s, 8);

    __syncthreads();
    if (g == 0) {
        float den = M.s + __logf(M.p.x) + s_fin_sh;   // alpha0=[1,0] in prob space
        resv[b] = np - den;
    }
    __syncthreads();

    float vv = (tid < BB) ? resv[tid] : 0.f;
#pragma unroll
    for (int o = 16; o; o >>= 1) vv += __shfl_xor_sync(0xffffffffu, vv, o);
    if (lane == 0) red[wid] = vv;
    __syncthreads();
    if (tid == 0) {
        float tsum = 0.f;
#pragma unroll
        for (int i = 0; i < 32; i++) tsum += red[i];
        out[0] = tsum;
    }
}

// ---------------- launcher ----------------
extern "C" void kernel_launch(void* const* d_in, const int* in_sizes, int n_in,
                              void* d_out, int out_size) {
    const float* lp     = (const float*)d_in[0];
    const float* dp     = (const float*)d_in[1];
    const int*   lens   = (const int*)d_in[2];
    const int*   labels = (const int*)d_in[3];

    dim3 grid(CHB, BB);
    k1_main<<<grid, 128>>>(lp, dp, lens, labels);
    k2_final<<<1, 1024>>>(dp, (float*)d_out);
}

// round 9
// speedup vs baseline: 1.4413x; 1.0968x over previous
#include <cuda_runtime.h>
#include <cstdint>

#define TT 4096
#define BB 128
#define CC 46
#define LL 43
#define NCH 4                 /* chunks (of 32 timesteps per warp) per block */
#define CHB 8                 /* blocks per batch = TT/(128*NCH) */
#define NINF (-3.4e38f)
#define LN2F 0.6931471805599453f

// ---------------- scratch (static device globals; no allocation) ----------------
__device__ float4 g_cmats[BB * CHB];
__device__ int    g_cexp[BB * CHB];
__device__ float  g_numpart[BB * CHB];

// ---------------- scaled-probability semiring matrix ----------------
// value = 2^e * P, P 2x2 row-major: x=00, y=01, z=10, w=11, max entry in [1,2).
struct SMat { float4 p; int e; };

// C = A (later) * B (earlier): 8 FFMA + integer exponent renorm (no MUFU).
__device__ __forceinline__ SMat smul(const SMat A, const SMat B) {
    SMat C;
    C.p.x = fmaf(A.p.x, B.p.x, A.p.y * B.p.z);
    C.p.y = fmaf(A.p.x, B.p.y, A.p.y * B.p.w);
    C.p.z = fmaf(A.p.z, B.p.x, A.p.w * B.p.z);
    C.p.w = fmaf(A.p.z, B.p.y, A.p.w * B.p.w);
    float mx = fmaxf(fmaxf(C.p.x, C.p.y), fmaxf(C.p.z, C.p.w));
    int   k  = (__float_as_int(mx) >> 23) & 255;         // biased exponent of mx
    float r  = __int_as_float((254 - k) << 23);          // exact 2^(127-k)
    C.p.x *= r; C.p.y *= r; C.p.z *= r; C.p.w *= r;
    C.e = A.e + B.e + (k - 127);
    return C;
}

__device__ __forceinline__ SMat shfl_down_m(const SMat v, int s, int w) {
    SMat r;
    r.p.x = __shfl_down_sync(0xffffffffu, v.p.x, s, w);
    r.p.y = __shfl_down_sync(0xffffffffu, v.p.y, s, w);
    r.p.z = __shfl_down_sync(0xffffffffu, v.p.z, s, w);
    r.p.w = __shfl_down_sync(0xffffffffu, v.p.w, s, w);
    r.e   = __shfl_down_sync(0xffffffffu, v.e,   s, w);
    return r;
}

__device__ __forceinline__ void cp16(uint32_t dst, const float4* src) {
    asm volatile("cp.async.cg.shared.global [%0], [%1], 16;\n" :: "r"(dst), "l"(src));
}

// ---------------- k1: warp-private pipelined streaming kernel ----------------
__global__ void __launch_bounds__(128) k1_main(
    const float* __restrict__ lp,
    const float* __restrict__ dp,
    const int* __restrict__ lens,
    const int* __restrict__ labels)
{
    __shared__ float  tiles[2][128 * CC];   // 2 x 23552 B; warp w rows [32w,32w+32)
    __shared__ float2 wab[CC];              // (w0, w1) per column; cols 0,2 zeroed
    __shared__ float  scs[2];               // [0]=exp(s_0I), [1]=exp(s_1I)
    __shared__ float4 warpP[4];
    __shared__ int    warpE[4];
    __shared__ float  warpT[4];

    const int tid  = threadIdx.x;
    const int lane = tid & 31;
    const int wid  = tid >> 5;
    const int b    = blockIdx.y;
    const int t0   = blockIdx.x * (128 * NCH);

    const float4* __restrict__ base4 =
        (const float4*)(lp + ((size_t)b * TT + t0) * CC) + (size_t)wid * 1472;
    const uint32_t smA = (uint32_t)__cvta_generic_to_shared(&tiles[0][0]) + wid * 368 * 16;
    const uint32_t smB = (uint32_t)__cvta_generic_to_shared(&tiles[1][0]) + wid * 368 * 16;

    // --- warp-local prefetch of chunk 0 (368 float4 per warp) ---
#pragma unroll
    for (int k = 0; k < 12; k++) {
        int i = lane + 32 * k;
        if (i < 368) cp16(smA + i * 16, base4 + i);
    }
    asm volatile("cp.async.commit_group;\n");

    // --- warp 0: params (overlaps prefetch latency) ---
    if (wid == 0) {
        float a  = dp[lane];
        float bb = (lane + 32 < CC) ? dp[lane + 32] : NINF;
        float m = fmaxf(a, bb);
#pragma unroll
        for (int o = 16; o; o >>= 1) m = fmaxf(m, __shfl_xor_sync(0xffffffffu, m, o));
        float s = __expf(a - m) + __expf(bb - m);
#pragma unroll
        for (int o = 16; o; o >>= 1) s += __shfl_xor_sync(0xffffffffu, s, o);
        const float lz0 = m + __logf(s);
        float a1 = (lane < LL + 1) ? dp[CC + lane] : NINF;
        float b1 = (lane + 32 < LL + 1) ? dp[CC + lane + 32] : NINF;
        float m1 = fmaxf(a1, b1);
#pragma unroll
        for (int o = 16; o; o >>= 1) m1 = fmaxf(m1, __shfl_xor_sync(0xffffffffu, m1, o));
        float s1 = __expf(a1 - m1) + __expf(b1 - m1);
#pragma unroll
        for (int o = 16; o; o >>= 1) s1 += __shfl_xor_sync(0xffffffffu, s1, o);
        const float lz1 = m1 + __logf(s1);
#pragma unroll
        for (int c = lane; c < CC; c += 32) {
            float w0 = 0.f, w1 = 0.f;
            if (c == 1) w0 = __expf(dp[0] - lz0);          // exp(s_O): folds s_O+lp1 into S0
            if (c >= 3) {
                w0 = __expf(dp[c - 2] - lz0);              // exp(s0_lab)
                w1 = __expf(dp[CC + c - 2] - lz1);         // exp(s1_lab)
            }
            wab[c] = make_float2(w0, w1);
        }
        if (lane == 0) {
            scs[0] = __expf(dp[LL + 1] - lz0);   // exp(s_0I)
            scs[1] = __expf(dp[CC] - lz1);       // exp(s_1I)
        }
    }
    __syncthreads();   // wab/scs visible; no more block barriers until the end

    // release the dependent k2 launch as early as possible (PDL)
    cudaTriggerProgrammaticLaunchCompletion();

    const int len = lens[b];
    const float k0 = scs[0], k1c = scs[1];
    float tok_acc = 0.f;
    SMat run;   // meaningful on lane 0 of each warp

    for (int c = 0; c < NCH; c++) {
        if (c + 1 < NCH) {
            const uint32_t dsm = ((c + 1) & 1) ? smB : smA;
            const float4* src = base4 + (size_t)(c + 1) * 368;
#pragma unroll
            for (int k = 0; k < 12; k++) {
                int i = lane + 32 * k;
                if (i < 368) cp16(dsm + i * 16, src + i);
            }
            asm volatile("cp.async.commit_group;\n");
            asm volatile("cp.async.wait_group 1;\n");
        } else {
            asm volatile("cp.async.wait_group 0;\n");
        }
        __syncwarp();   // warp-local buffer ownership

        const float* rowp = tiles[c & 1] + tid * CC;
        const int t = t0 + wid * 128 + c * 32 + lane;
        const int lab = labels[(size_t)b * TT + t];
        const bool valid = t < len;

        // stream 23 float2: exp directly (log-softmax inputs <= 0: no overflow)
        float S0a = 0.f, S0b = 0.f, S1a = 0.f, S1b = 0.f, e2 = 0.f;
        const float2* r2 = (const float2*)rowp;
#pragma unroll
        for (int i = 0; i < 23; i++) {
            float2 q = r2[i];
            float ex = __expf(q.x);
            float ey = __expf(q.y);
            if (i == 1) e2 = ex;                       // exp(lp[2])
            float2 wA = wab[2 * i];
            float2 wB = wab[2 * i + 1];
            S0a = fmaf(ex, wA.x, S0a); S1a = fmaf(ex, wA.y, S1a);
            S0b = fmaf(ey, wB.x, S0b); S1b = fmaf(ey, wB.y, S1b);
        }
        tok_acc += valid ? rowp[lab] : 0.f;

        SMat M;
        if (valid) {
            M.p = make_float4(S0a + S0b, S1a + S1b, e2 * k0, e2 * k1c);
        } else {
            M.p = make_float4(1.f, 0.f, 0.f, 1.f);
        }
        M.e = 0;

        // warp-level ordered fold over 32 consecutive timesteps (MUFU-free)
#pragma unroll
        for (int s = 1; s < 32; s <<= 1) {
            SMat o = shfl_down_m(M, s, 32);
            if ((lane & (2 * s - 1)) == 0) M = smul(o, M);
        }
        run = (c == 0) ? M : smul(M, run);   // valid on lane 0
    }

    // token warp sum; publish per-warp results
#pragma unroll
    for (int o = 16; o; o >>= 1) tok_acc += __shfl_xor_sync(0xffffffffu, tok_acc, o);
    if (lane == 0) { warpP[wid] = run.p; warpE[wid] = run.e; warpT[wid] = tok_acc; }
    __syncthreads();

    if (wid == 0) {
        SMat A;
        if (lane < 4) { A.p = warpP[lane]; A.e = warpE[lane]; }
        else          { A.p = make_float4(1.f, 0.f, 0.f, 1.f); A.e = 0; }
#pragma unroll
        for (int s = 1; s < 4; s <<= 1) {
            SMat o = shfl_down_m(A, s, 4);
            if ((lane & (2 * s - 1)) == 0 && lane + s < 4) A = smul(o, A);
        }
        if (lane == 0) {
            const int slot = b * CHB + blockIdx.x;
            g_cmats[slot]   = A.p;
            g_cexp[slot]    = A.e;
            g_numpart[slot] = warpT[0] + warpT[1] + warpT[2] + warpT[3];
        }
    }
}

// ---------------- k2: chunk reduce + den + num + global sum (PDL secondary) ----
__global__ void __launch_bounds__(1024) k2_final(
    const float* __restrict__ dp, float* __restrict__ out)
{
    const int tid  = threadIdx.x;
    const int lane = tid & 31;
    const int wid  = tid >> 5;
    __shared__ float s_fin_sh;
    __shared__ float resv[BB];
    __shared__ float red[32];

    // dp-only prologue: overlaps k1 execution (before grid sync)
    if (wid == 0) {
        float a  = dp[lane];
        float bb = (lane + 32 < CC) ? dp[lane + 32] : NINF;
        float m = fmaxf(a, bb);
#pragma unroll
        for (int o = 16; o; o >>= 1) m = fmaxf(m, __shfl_xor_sync(0xffffffffu, m, o));
        float s = __expf(a - m) + __expf(bb - m);
#pragma unroll
        for (int o = 16; o; o >>= 1) s += __shfl_xor_sync(0xffffffffu, s, o);
        if (lane == 0) s_fin_sh = dp[LL + 2] - (m + __logf(s));
    }

    // wait for k1's gmem results to be visible
    cudaGridDependencySynchronize();

    const int b = tid >> 3;
    const int g = tid & 7;
    SMat M;
    M.p = g_cmats[b * CHB + g];
    M.e = g_cexp[b * CHB + g];
    float np = g_numpart[b * CHB + g];

#pragma unroll
    for (int s = 1; s < 8; s <<= 1) {
        SMat o = shfl_down_m(M, s, 8);
        if ((g & (2 * s - 1)) == 0) M = smul(o, M);
    }
#pragma unroll
    for (int s = 4; s; s >>= 1) np += __shfl_down_sync(0xffffffffu, np, s, 8);

    __syncthreads();
    if (g == 0) {
        // alpha0=[1,0]: den = e*ln2 + log(P00) + s_fin
        float den = (float)M.e * LN2F + __logf(M.p.x) + s_fin_sh;
        resv[b] = np - den;
    }
    __syncthreads();

    float vv = (tid < BB) ? resv[tid] : 0.f;
#pragma unroll
    for (int o = 16; o; o >>= 1) vv += __shfl_xor_sync(0xffffffffu, vv, o);
    if (lane == 0) red[wid] = vv;
    __syncthreads();
    if (tid == 0) {
        float tsum = 0.f;
#pragma unroll
        for (int i = 0; i < 32; i++) tsum += red[i];
        out[0] = tsum;
    }
}

// ---------------- launcher ----------------
extern "C" void kernel_launch(void* const* d_in, const int* in_sizes, int n_in,
                              void* d_out, int out_size) {
    const float* lp     = (const float*)d_in[0];
    const float* dp     = (const float*)d_in[1];
    const int*   lens   = (const int*)d_in[2];
    const int*   labels = (const int*)d_in[3];

    dim3 grid(CHB, BB);
    k1_main<<<grid, 128>>>(lp, dp, lens, labels);

    // PDL launch of k2: overlaps its launch latency with k1 execution
    cudaLaunchConfig_t cfg = {};
    cfg.gridDim  = dim3(1, 1, 1);
    cfg.blockDim = dim3(1024, 1, 1);
    cfg.dynamicSmemBytes = 0;
    cfg.stream = 0;
    cudaLaunchAttribute attrs[1];
    attrs[0].id = cudaLaunchAttributeProgrammaticStreamSerialization;
    attrs[0].val.programmaticStreamSerializationAllowed = 1;
    cfg.attrs = attrs;
    cfg.numAttrs = 1;
    cudaLaunchKernelEx(&cfg, k2_final, dp, (float*)d_out);
}

// round 10
// speedup vs baseline: 1.5008x; 1.0412x over previous
#include <cuda_runtime.h>
#include <cstdint>

#define TT 4096
#define BB 128
#define CC 46
#define LL 43
#define NCH 8                 /* chunks (of 32 timesteps per warp) per block */
#define CHB 4                 /* blocks per batch = TT/(128*NCH) */
#define NINF (-3.4e38f)
#define LN2F 0.6931471805599453f

// ---------------- scratch (static device globals; no allocation) ----------------
__device__ float4 g_cmats[BB * CHB];
__device__ int    g_cexp[BB * CHB];
__device__ float  g_numpart[BB * CHB];

// ---------------- scaled-probability semiring matrix ----------------
// value = 2^e * P, P 2x2 row-major: x=00, y=01, z=10, w=11, max entry in [1,2).
struct SMat { float4 p; int e; };

// C = A (later) * B (earlier): 8 FFMA + integer exponent renorm (no MUFU).
__device__ __forceinline__ SMat smul(const SMat A, const SMat B) {
    SMat C;
    C.p.x = fmaf(A.p.x, B.p.x, A.p.y * B.p.z);
    C.p.y = fmaf(A.p.x, B.p.y, A.p.y * B.p.w);
    C.p.z = fmaf(A.p.z, B.p.x, A.p.w * B.p.z);
    C.p.w = fmaf(A.p.z, B.p.y, A.p.w * B.p.w);
    float mx = fmaxf(fmaxf(C.p.x, C.p.y), fmaxf(C.p.z, C.p.w));
    int   k  = (__float_as_int(mx) >> 23) & 255;         // biased exponent of mx
    float r  = __int_as_float((254 - k) << 23);          // exact 2^(127-k)
    C.p.x *= r; C.p.y *= r; C.p.z *= r; C.p.w *= r;
    C.e = A.e + B.e + (k - 127);
    return C;
}

__device__ __forceinline__ SMat shfl_down_m(const SMat v, int s, int w) {
    SMat r;
    r.p.x = __shfl_down_sync(0xffffffffu, v.p.x, s, w);
    r.p.y = __shfl_down_sync(0xffffffffu, v.p.y, s, w);
    r.p.z = __shfl_down_sync(0xffffffffu, v.p.z, s, w);
    r.p.w = __shfl_down_sync(0xffffffffu, v.p.w, s, w);
    r.e   = __shfl_down_sync(0xffffffffu, v.e,   s, w);
    return r;
}

__device__ __forceinline__ void cp16(uint32_t dst, const float4* src) {
    asm volatile("cp.async.cg.shared.global [%0], [%1], 16;\n" :: "r"(dst), "l"(src));
}

// ---------------- k1: warp-private pipelined streaming kernel ----------------
// grid (CHB, BB), block 128 threads. Block covers 1024 timesteps; warp w owns
// the contiguous range [t0+256w, t0+256w+256), processed as NCH chunks of 32.
__global__ void __launch_bounds__(128) k1_main(
    const float* __restrict__ lp,
    const float* __restrict__ dp,
    const int* __restrict__ lens,
    const int* __restrict__ labels)
{
    __shared__ float  tiles[2][128 * CC];   // 2 x 23552 B; warp w rows [32w,32w+32)
    __shared__ float2 wab[CC];              // (w0, w1) per column; cols 0,2 zeroed
    __shared__ float  scs[2];               // [0]=exp(s_0I), [1]=exp(s_1I)
    __shared__ float4 warpP[4];
    __shared__ int    warpE[4];
    __shared__ float  warpT[4];

    const int tid  = threadIdx.x;
    const int lane = tid & 31;
    const int wid  = tid >> 5;
    const int b    = blockIdx.y;
    const int t0   = blockIdx.x * (128 * NCH);

    // warp w's 256-timestep segment: offset wid * 256 * 46 / 4 = wid * 2944 float4
    const float4* __restrict__ base4 =
        (const float4*)(lp + ((size_t)b * TT + t0) * CC) + (size_t)wid * 2944;
    const uint32_t smA = (uint32_t)__cvta_generic_to_shared(&tiles[0][0]) + wid * 368 * 16;
    const uint32_t smB = (uint32_t)__cvta_generic_to_shared(&tiles[1][0]) + wid * 368 * 16;

    // --- warp-local prefetch of chunk 0 (368 float4 per warp) ---
#pragma unroll
    for (int k = 0; k < 12; k++) {
        int i = lane + 32 * k;
        if (i < 368) cp16(smA + i * 16, base4 + i);
    }
    asm volatile("cp.async.commit_group;\n");

    // --- warp 0: params (overlaps prefetch latency) ---
    if (wid == 0) {
        float a  = dp[lane];
        float bb = (lane + 32 < CC) ? dp[lane + 32] : NINF;
        float m = fmaxf(a, bb);
#pragma unroll
        for (int o = 16; o; o >>= 1) m = fmaxf(m, __shfl_xor_sync(0xffffffffu, m, o));
        float s = __expf(a - m) + __expf(bb - m);
#pragma unroll
        for (int o = 16; o; o >>= 1) s += __shfl_xor_sync(0xffffffffu, s, o);
        const float lz0 = m + __logf(s);
        float a1 = (lane < LL + 1) ? dp[CC + lane] : NINF;
        float b1 = (lane + 32 < LL + 1) ? dp[CC + lane + 32] : NINF;
        float m1 = fmaxf(a1, b1);
#pragma unroll
        for (int o = 16; o; o >>= 1) m1 = fmaxf(m1, __shfl_xor_sync(0xffffffffu, m1, o));
        float s1 = __expf(a1 - m1) + __expf(b1 - m1);
#pragma unroll
        for (int o = 16; o; o >>= 1) s1 += __shfl_xor_sync(0xffffffffu, s1, o);
        const float lz1 = m1 + __logf(s1);
#pragma unroll
        for (int c = lane; c < CC; c += 32) {
            float w0 = 0.f, w1 = 0.f;
            if (c == 1) w0 = __expf(dp[0] - lz0);          // exp(s_O): folds s_O+lp1 into S0
            if (c >= 3) {
                w0 = __expf(dp[c - 2] - lz0);              // exp(s0_lab)
                w1 = __expf(dp[CC + c - 2] - lz1);         // exp(s1_lab)
            }
            wab[c] = make_float2(w0, w1);
        }
        if (lane == 0) {
            scs[0] = __expf(dp[LL + 1] - lz0);   // exp(s_0I)
            scs[1] = __expf(dp[CC] - lz1);       // exp(s_1I)
        }
    }
    __syncthreads();   // wab/scs visible; no more block barriers until the end

    // release the dependent k2 launch as early as possible (PDL)
    cudaTriggerProgrammaticLaunchCompletion();

    const int len = lens[b];
    const float k0 = scs[0], k1c = scs[1];
    float tok_acc = 0.f;
    SMat run;   // meaningful on lane 0 of each warp

    for (int c = 0; c < NCH; c++) {
        if (c + 1 < NCH) {
            const uint32_t dsm = ((c + 1) & 1) ? smB : smA;
            const float4* src = base4 + (size_t)(c + 1) * 368;
#pragma unroll
            for (int k = 0; k < 12; k++) {
                int i = lane + 32 * k;
                if (i < 368) cp16(dsm + i * 16, src + i);
            }
            asm volatile("cp.async.commit_group;\n");
            asm volatile("cp.async.wait_group 1;\n");
        } else {
            asm volatile("cp.async.wait_group 0;\n");
        }
        __syncwarp();   // warp-local buffer ownership

        const float* rowp = tiles[c & 1] + tid * CC;
        const int t = t0 + wid * 256 + c * 32 + lane;
        const int lab = labels[(size_t)b * TT + t];
        const bool valid = t < len;

        // stream 23 float2: exp directly (log-softmax inputs <= 0: no overflow)
        float S0a = 0.f, S0b = 0.f, S1a = 0.f, S1b = 0.f, e2 = 0.f;
        const float2* r2 = (const float2*)rowp;
#pragma unroll
        for (int i = 0; i < 23; i++) {
            float2 q = r2[i];
            float ex = __expf(q.x);
            float ey = __expf(q.y);
            if (i == 1) e2 = ex;                       // exp(lp[2])
            float2 wA = wab[2 * i];
            float2 wB = wab[2 * i + 1];
            S0a = fmaf(ex, wA.x, S0a); S1a = fmaf(ex, wA.y, S1a);
            S0b = fmaf(ey, wB.x, S0b); S1b = fmaf(ey, wB.y, S1b);
        }
        tok_acc += valid ? rowp[lab] : 0.f;

        SMat M;
        if (valid) {
            M.p = make_float4(S0a + S0b, S1a + S1b, e2 * k0, e2 * k1c);
        } else {
            M.p = make_float4(1.f, 0.f, 0.f, 1.f);
        }
        M.e = 0;

        // warp-level ordered fold over 32 consecutive timesteps (MUFU-free)
#pragma unroll
        for (int s = 1; s < 32; s <<= 1) {
            SMat o = shfl_down_m(M, s, 32);
            if ((lane & (2 * s - 1)) == 0) M = smul(o, M);
        }
        run = (c == 0) ? M : smul(M, run);   // valid on lane 0
    }

    // token warp sum; publish per-warp results
#pragma unroll
    for (int o = 16; o; o >>= 1) tok_acc += __shfl_xor_sync(0xffffffffu, tok_acc, o);
    if (lane == 0) { warpP[wid] = run.p; warpE[wid] = run.e; warpT[wid] = tok_acc; }
    __syncthreads();

    if (wid == 0) {
        SMat A;
        if (lane < 4) { A.p = warpP[lane]; A.e = warpE[lane]; }
        else          { A.p = make_float4(1.f, 0.f, 0.f, 1.f); A.e = 0; }
#pragma unroll
        for (int s = 1; s < 4; s <<= 1) {
            SMat o = shfl_down_m(A, s, 4);
            if ((lane & (2 * s - 1)) == 0 && lane + s < 4) A = smul(o, A);
        }
        if (lane == 0) {
            const int slot = b * CHB + blockIdx.x;
            g_cmats[slot]   = A.p;
            g_cexp[slot]    = A.e;
            g_numpart[slot] = warpT[0] + warpT[1] + warpT[2] + warpT[3];
        }
    }
}

// ---------------- k2: chunk reduce + den + num + global sum (PDL secondary) ----
// one block, 512 threads; 4 lanes per batch (128 batches x 4 chunk slots).
__global__ void __launch_bounds__(512) k2_final(
    const float* __restrict__ dp, float* __restrict__ out)
{
    const int tid  = threadIdx.x;
    const int lane = tid & 31;
    const int wid  = tid >> 5;
    __shared__ float s_fin_sh;
    __shared__ float resv[BB];
    __shared__ float red[16];

    // dp-only prologue: overlaps k1 execution (before grid sync)
    if (wid == 0) {
        float a  = dp[lane];
        float bb = (lane + 32 < CC) ? dp[lane + 32] : NINF;
        float m = fmaxf(a, bb);
#pragma unroll
        for (int o = 16; o; o >>= 1) m = fmaxf(m, __shfl_xor_sync(0xffffffffu, m, o));
        float s = __expf(a - m) + __expf(bb - m);
#pragma unroll
        for (int o = 16; o; o >>= 1) s += __shfl_xor_sync(0xffffffffu, s, o);
        if (lane == 0) s_fin_sh = dp[LL + 2] - (m + __logf(s));
    }

    // wait for k1's gmem results to be visible
    cudaGridDependencySynchronize();

    const int b = tid >> 2;          // 0..127
    const int g = tid & 3;           // 0..3
    SMat M;
    M.p = g_cmats[b * CHB + g];
    M.e = g_cexp[b * CHB + g];
    float np = g_numpart[b * CHB + g];

#pragma unroll
    for (int s = 1; s < 4; s <<= 1) {
        SMat o = shfl_down_m(M, s, 4);
        if ((g & (2 * s - 1)) == 0) M = smul(o, M);
    }
#pragma unroll
    for (int s = 2; s; s >>= 1) np += __shfl_down_sync(0xffffffffu, np, s, 4);

    __syncthreads();
    if (g == 0) {
        // alpha0=[1,0]: den = e*ln2 + log(P00) + s_fin
        float den = (float)M.e * LN2F + __logf(M.p.x) + s_fin_sh;
        resv[b] = np - den;
    }
    __syncthreads();

    float vv = (tid < BB) ? resv[tid] : 0.f;
#pragma unroll
    for (int o = 16; o; o >>= 1) vv += __shfl_xor_sync(0xffffffffu, vv, o);
    if (lane == 0) red[wid] = vv;
    __syncthreads();
    if (tid == 0) {
        float tsum = 0.f;
#pragma unroll
        for (int i = 0; i < 4; i++) tsum += red[i];   // only warps 0-3 hold BB values
        out[0] = tsum;
    }
}

// ---------------- launcher ----------------
extern "C" void kernel_launch(void* const* d_in, const int* in_sizes, int n_in,
                              void* d_out, int out_size) {
    const float* lp     = (const float*)d_in[0];
    const float* dp     = (const float*)d_in[1];
    const int*   lens   = (const int*)d_in[2];
    const int*   labels = (const int*)d_in[3];

    dim3 grid(CHB, BB);
    k1_main<<<grid, 128>>>(lp, dp, lens, labels);

    // PDL launch of k2: overlaps its launch latency with k1 execution
    cudaLaunchConfig_t cfg = {};
    cfg.gridDim  = dim3(1, 1, 1);
    cfg.blockDim = dim3(512, 1, 1);
    cfg.dynamicSmemBytes = 0;
    cfg.stream = 0;
    cudaLaunchAttribute attrs[1];
    attrs[0].id = cudaLaunchAttributeProgrammaticStreamSerialization;
    attrs[0].val.programmaticStreamSerializationAllowed = 1;
    cfg.attrs = attrs;
    cfg.numAttrs = 1;
    cudaLaunchKernelEx(&cfg, k2_final, dp, (float*)d_out);
}